// round 2
// baseline (speedup 1.0000x reference)
#include <cuda_runtime.h>
#include <cuda_bf16.h>
#include <cstdint>

#define N_NODES 50000
#define FEATS   64
#define N_EDGES 800000
#define SCAN_B  1024
#define N_CHUNK ((N_NODES + SCAN_B - 1) / SCAN_B)   // 49

typedef unsigned long long u64;

// -------- scratch (device globals; no allocation allowed) --------
__device__ int g_idx32;                 // 1 if indices are int32, 0 if int64
__device__ int g_deg[N_NODES];
__device__ int g_rowptr[N_NODES + 1];
__device__ int g_blocksum[64];
__device__ int g_blockoff[64];
__device__ int g_fill[N_NODES];
__device__ int g_src32[N_EDGES];
__device__ int g_dst32[N_EDGES];
__device__ int g_col[N_EDGES];
__device__ __align__(16) float g_agg[N_NODES * FEATS];
__device__ __align__(16) float g_h1 [N_NODES * FEATS];
__device__ __align__(16) float g_h2 [N_NODES * FEATS];

// -------- packed f32x2 helpers --------
__device__ __forceinline__ void ffma2(u64& d, u64 a, u64 b, u64 c) {
    asm("fma.rn.f32x2 %0, %1, %2, %3;" : "=l"(d) : "l"(a), "l"(b), "l"(c));
}
__device__ __forceinline__ u64 splat2(float x) {
    u64 r; unsigned u = __float_as_uint(x);
    asm("mov.b64 %0, {%1, %1};" : "=l"(r) : "r"(u));
    return r;
}
__device__ __forceinline__ u64 pack2(float lo, float hi) {
    u64 r; unsigned a = __float_as_uint(lo), b = __float_as_uint(hi);
    asm("mov.b64 %0, {%1, %2};" : "=l"(r) : "r"(a), "r"(b));
    return r;
}
__device__ __forceinline__ float2 unpack2(u64 v) {
    unsigned a, b;
    asm("mov.b64 {%0, %1}, %2;" : "=r"(a), "=r"(b) : "l"(v));
    return make_float2(__uint_as_float(a), __uint_as_float(b));
}

// -------- prep: zero + dtype detection (item_ids == arange) --------
// int32 layout: words 0,1,2,...  -> word[2]==2 ; int64: 0,0,1,0,... -> word[2]==1
__global__ void k_zero(const int* ids_words) {
    int i = blockIdx.x * blockDim.x + threadIdx.x;
    if (i == 0) g_idx32 = (ids_words[2] == 2) ? 1 : 0;
    if (i < N_NODES) { g_deg[i] = 0; g_fill[i] = 0; }
}

__device__ __forceinline__ int read_idx(const void* p, int i) {
    return g_idx32 ? ((const int*)p)[i] : (int)((const long long*)p)[i];
}

// degree histogram + stash int32-converted indices (so fill re-reads 32-bit)
__global__ void k_degree(const void* __restrict__ src, const void* __restrict__ dst) {
    int i = blockIdx.x * blockDim.x + threadIdx.x;
    if (i >= N_EDGES) return;
    int d = read_idx(dst, i);
    int s = read_idx(src, i);
    g_dst32[i] = d;
    g_src32[i] = s;
    atomicAdd(&g_deg[d], 1);
}

// -------- shuffle-based scan --------
__global__ void k_scan1() {
    __shared__ int wsum[32];
    int tid = threadIdx.x;
    int lane = tid & 31, wid = tid >> 5;
    int gid = blockIdx.x * SCAN_B + tid;
    int x = (gid < N_NODES) ? g_deg[gid] : 0;
    #pragma unroll
    for (int off = 1; off < 32; off <<= 1) {
        int t = __shfl_up_sync(0xffffffff, x, off);
        if (lane >= off) x += t;
    }
    if (lane == 31) wsum[wid] = x;
    __syncthreads();
    if (wid == 0) {
        int s = wsum[lane];
        #pragma unroll
        for (int off = 1; off < 32; off <<= 1) {
            int t = __shfl_up_sync(0xffffffff, s, off);
            if (lane >= off) s += t;
        }
        wsum[lane] = s;
    }
    __syncthreads();
    if (wid > 0) x += wsum[wid - 1];
    if (gid < N_NODES) g_rowptr[gid + 1] = x;
    if (tid == SCAN_B - 1) g_blocksum[blockIdx.x] = x;
    if (gid == 0) g_rowptr[0] = 0;
}

__global__ void k_scan2(int nb) {
    // 64 elements, 2 warps; simple shared-mem scan
    __shared__ int sh[64];
    int tid = threadIdx.x;
    int v = (tid < nb) ? g_blocksum[tid] : 0;
    sh[tid] = v;
    __syncthreads();
    #pragma unroll
    for (int off = 1; off < 64; off <<= 1) {
        int t = (tid >= off) ? sh[tid - off] : 0;
        __syncthreads();
        sh[tid] += t;
        __syncthreads();
    }
    g_blockoff[tid] = sh[tid] - v;   // exclusive
}

__global__ void k_scan3() {
    int gid = blockIdx.x * SCAN_B + threadIdx.x;
    if (gid < N_NODES) g_rowptr[gid + 1] += g_blockoff[blockIdx.x];
}

__global__ void k_fill() {
    int i = blockIdx.x * blockDim.x + threadIdx.x;
    if (i >= N_EDGES) return;
    int d = g_dst32[i];
    int pos = g_rowptr[d] + atomicAdd(&g_fill[d], 1);
    g_col[pos] = g_src32[i];
}

// -------- mean aggregation: one warp per node, lane owns 2 feats, MLP=4 --------
__global__ void k_agg(const float* __restrict__ h, float* __restrict__ agg) {
    int warp = (blockIdx.x * blockDim.x + threadIdx.x) >> 5;
    int lane = threadIdx.x & 31;
    if (warp >= N_NODES) return;
    int s = g_rowptr[warp], e = g_rowptr[warp + 1];
    const float2* h2 = (const float2*)h;
    float2 a0 = make_float2(0.f, 0.f), a1 = make_float2(0.f, 0.f);
    float2 a2 = make_float2(0.f, 0.f), a3 = make_float2(0.f, 0.f);
    int j = s;
    for (; j + 3 < e; j += 4) {
        int c0 = g_col[j], c1 = g_col[j + 1], c2 = g_col[j + 2], c3 = g_col[j + 3];
        float2 v0 = h2[c0 * 32 + lane];
        float2 v1 = h2[c1 * 32 + lane];
        float2 v2 = h2[c2 * 32 + lane];
        float2 v3 = h2[c3 * 32 + lane];
        a0.x += v0.x; a0.y += v0.y;
        a1.x += v1.x; a1.y += v1.y;
        a2.x += v2.x; a2.y += v2.y;
        a3.x += v3.x; a3.y += v3.y;
    }
    for (; j < e; j++) {
        int c = g_col[j];
        float2 v = h2[c * 32 + lane];
        a0.x += v.x; a0.y += v.y;
    }
    int deg = e - s;
    float inv = (deg > 0) ? (1.0f / (float)deg) : 0.0f;
    float2 o;
    o.x = ((a0.x + a1.x) + (a2.x + a3.x)) * inv;
    o.y = ((a0.y + a1.y) + (a2.y + a3.y)) * inv;
    ((float2*)agg)[warp * 32 + lane] = o;
}

// -------- fused transform with packed f32x2 FMA --------
// C = act(H@Ws [+ G@Wn] + b), 64-node tiles, smem H stride padded to 68 floats
#define HSTRIDE 68   // floats; 17 float4 per row; kills 2-way bank conflict
template <bool NEIGH, bool RELU>
__global__ void __launch_bounds__(256)
k_transform(const float* __restrict__ H, const float* __restrict__ G,
            const float* __restrict__ Ws, const float* __restrict__ Wn,
            const float* __restrict__ bias, float* __restrict__ C) {
    extern __shared__ float sm[];
    float* sWs = sm;                               // 4096 floats
    float* sWn = NEIGH ? (sm + 4096) : nullptr;    // 4096 floats
    float* sH  = NEIGH ? (sm + 8192) : (sm + 4096);  // 64*HSTRIDE
    float* sG  = NEIGH ? (sH + 64 * HSTRIDE) : nullptr;

    int tid = threadIdx.x;
    int n0 = blockIdx.x * 64;

    // load weights (1024 float4 each)
    #pragma unroll
    for (int i = 0; i < 4; i++) {
        int f = tid + i * 256;
        ((float4*)sWs)[f] = ((const float4*)Ws)[f];
        if (NEIGH) ((float4*)sWn)[f] = ((const float4*)Wn)[f];
    }
    // load node tiles (64 rows x 16 float4, padded stride 17 float4)
    #pragma unroll
    for (int i = 0; i < 4; i++) {
        int f = tid + i * 256;
        int row = f >> 4, c = f & 15;
        long g4 = (long)n0 * 16 + f;
        bool ok = (g4 < (long)N_NODES * 16);
        float4 v = ok ? ((const float4*)H)[g4] : make_float4(0.f, 0.f, 0.f, 0.f);
        ((float4*)sH)[row * 17 + c] = v;
        if (NEIGH) {
            float4 u = ok ? ((const float4*)G)[g4] : make_float4(0.f, 0.f, 0.f, 0.f);
            ((float4*)sG)[row * 17 + c] = u;
        }
    }
    __syncthreads();

    int tx = tid & 15;    // output group (4 outputs = 2 packed pairs)
    int ty = tid >> 4;    // node group (4 nodes)

    float4 bv = ((const float4*)bias)[tx];
    u64 acc[4][2];
    u64 b01 = pack2(bv.x, bv.y), b23 = pack2(bv.z, bv.w);
    #pragma unroll
    for (int i = 0; i < 4; i++) { acc[i][0] = b01; acc[i][1] = b23; }

    #pragma unroll 4
    for (int k = 0; k < 64; k++) {
        ulonglong2 ws = ((const ulonglong2*)sWs)[k * 16 + tx];
        #pragma unroll
        for (int i = 0; i < 4; i++) {
            u64 h2 = splat2(sH[(ty * 4 + i) * HSTRIDE + k]);
            ffma2(acc[i][0], h2, ws.x, acc[i][0]);
            ffma2(acc[i][1], h2, ws.y, acc[i][1]);
        }
        if (NEIGH) {
            ulonglong2 wn = ((const ulonglong2*)sWn)[k * 16 + tx];
            #pragma unroll
            for (int i = 0; i < 4; i++) {
                u64 g2 = splat2(sG[(ty * 4 + i) * HSTRIDE + k]);
                ffma2(acc[i][0], g2, wn.x, acc[i][0]);
                ffma2(acc[i][1], g2, wn.y, acc[i][1]);
            }
        }
    }

    #pragma unroll
    for (int i = 0; i < 4; i++) {
        int row = n0 + ty * 4 + i;
        if (row < N_NODES) {
            float2 lo = unpack2(acc[i][0]);
            float2 hi = unpack2(acc[i][1]);
            float4 o;
            o.x = RELU ? fmaxf(lo.x, 0.f) : lo.x;
            o.y = RELU ? fmaxf(lo.y, 0.f) : lo.y;
            o.z = RELU ? fmaxf(hi.x, 0.f) : hi.x;
            o.w = RELU ? fmaxf(hi.y, 0.f) : hi.y;
            ((float4*)C)[row * 16 + tx] = o;
        }
    }
}

extern "C" void kernel_launch(void* const* d_in, const int* in_sizes, int n_in,
                              void* d_out, int out_size) {
    const float* embed   = (const float*)d_in[0];
    const float* W1_self = (const float*)d_in[1];
    const float* W1_neigh= (const float*)d_in[2];
    const float* b1      = (const float*)d_in[3];
    const float* W2_self = (const float*)d_in[4];
    const float* W2_neigh= (const float*)d_in[5];
    const float* b2      = (const float*)d_in[6];
    const float* W_fc    = (const float*)d_in[7];
    const float* b_fc    = (const float*)d_in[8];
    const int*   ids_w   = (const int*)d_in[9];
    const void*  src     = d_in[10];
    const void*  dst     = d_in[11];
    float* out = (float*)d_out;

    const int SMEM_N = (8192 + 2 * 64 * HSTRIDE) * 4;   // ~67.8KB (NEIGH)
    const int SMEM_F = (4096 + 64 * HSTRIDE) * 4;       // ~33.8KB (final)
    cudaFuncSetAttribute((const void*)k_transform<true, true>,
                         cudaFuncAttributeMaxDynamicSharedMemorySize, SMEM_N);
    cudaFuncSetAttribute((const void*)k_transform<true, false>,
                         cudaFuncAttributeMaxDynamicSharedMemorySize, SMEM_N);
    cudaFuncSetAttribute((const void*)k_transform<false, false>,
                         cudaFuncAttributeMaxDynamicSharedMemorySize, SMEM_F);

    float* agg; cudaGetSymbolAddress((void**)&agg, g_agg);
    float* h1;  cudaGetSymbolAddress((void**)&h1,  g_h1);
    float* h2;  cudaGetSymbolAddress((void**)&h2,  g_h2);

    // --- CSR build (once, reused by both layers) ---
    k_zero<<<(N_NODES + 255) / 256, 256>>>(ids_w);
    k_degree<<<(N_EDGES + 255) / 256, 256>>>(src, dst);
    k_scan1<<<N_CHUNK, SCAN_B>>>();
    k_scan2<<<1, 64>>>(N_CHUNK);
    k_scan3<<<N_CHUNK, SCAN_B>>>();
    k_fill<<<(N_EDGES + 255) / 256, 256>>>();

    const int AGG_BLOCKS = (N_NODES * 32 + 255) / 256;
    const int GEMM_BLOCKS = (N_NODES + 63) / 64;

    // --- Layer 1 ---
    k_agg<<<AGG_BLOCKS, 256>>>(embed, agg);
    k_transform<true, true><<<GEMM_BLOCKS, 256, SMEM_N>>>(
        embed, agg, W1_self, W1_neigh, b1, h1);

    // --- Layer 2 ---
    k_agg<<<AGG_BLOCKS, 256>>>(h1, agg);
    k_transform<true, false><<<GEMM_BLOCKS, 256, SMEM_N>>>(
        h1, agg, W2_self, W2_neigh, b2, h2);

    // --- Final linear ---
    k_transform<false, false><<<GEMM_BLOCKS, 256, SMEM_F>>>(
        h2, nullptr, W_fc, nullptr, b_fc, out);
}

// round 3
// speedup vs baseline: 1.0019x; 1.0019x over previous
#include <cuda_runtime.h>
#include <cuda_fp16.h>
#include <cstdint>

#define N_NODES 50000
#define FEATS   64
#define N_EDGES 800000
#define SCAN_B  1024
#define N_CHUNK ((N_NODES + SCAN_B - 1) / SCAN_B)   // 49
#define HSTRIDE 68   // padded smem row stride in floats (17 float4)

// -------- scratch (device globals; no allocation allowed) --------
__device__ int g_idx32;                 // 1 if indices int32, 0 if int64
__device__ int g_deg[N_NODES];
__device__ int g_rowptr[N_NODES + 1];
__device__ int g_blocksum[64];
__device__ int g_fill[N_NODES];
__device__ int g_src32[N_EDGES];
__device__ int g_dst32[N_EDGES];
__device__ int g_col[N_EDGES];
__device__ __align__(16) __half2 g_xh [N_NODES * 32];  // fp16 gather table (embed)
__device__ __align__(16) __half2 g_h1h[N_NODES * 32];  // fp16 gather table (h1)
__device__ __align__(16) float g_agg[N_NODES * FEATS];
__device__ __align__(16) float g_h1 [N_NODES * FEATS];
__device__ __align__(16) float g_h2 [N_NODES * FEATS];

// -------- prep: zero counters + dtype detect + embed->fp16 convert --------
// item_ids == arange: int32 words 0,1,2,... -> word[2]==2 ; int64 -> word[2]==1
__global__ void k_zero(const int* ids_words, const float* __restrict__ embed) {
    int i = blockIdx.x * blockDim.x + threadIdx.x;
    if (i == 0) g_idx32 = (ids_words[2] == 2) ? 1 : 0;
    if (i < N_NODES) { g_deg[i] = 0; g_fill[i] = 0; }
    if (i < N_NODES * 32) {
        float2 v = ((const float2*)embed)[i];
        g_xh[i] = __floats2half2_rn(v.x, v.y);
    }
}

__device__ __forceinline__ int read_idx(const void* p, int i) {
    return g_idx32 ? ((const int*)p)[i] : (int)((const long long*)p)[i];
}

// degree histogram + stash int32 indices (fill re-reads 32-bit)
__global__ void k_degree(const void* __restrict__ src, const void* __restrict__ dst) {
    int i = blockIdx.x * blockDim.x + threadIdx.x;
    if (i >= N_EDGES) return;
    int d = read_idx(dst, i);
    int s = read_idx(src, i);
    g_dst32[i] = d;
    g_src32[i] = s;
    atomicAdd(&g_deg[d], 1);
}

// -------- scan: per-chunk shfl scan, then per-block blocksum prefix --------
__global__ void k_scan1() {
    __shared__ int wsum[32];
    int tid = threadIdx.x;
    int lane = tid & 31, wid = tid >> 5;
    int gid = blockIdx.x * SCAN_B + tid;
    int x = (gid < N_NODES) ? g_deg[gid] : 0;
    #pragma unroll
    for (int off = 1; off < 32; off <<= 1) {
        int t = __shfl_up_sync(0xffffffff, x, off);
        if (lane >= off) x += t;
    }
    if (lane == 31) wsum[wid] = x;
    __syncthreads();
    if (wid == 0) {
        int s = wsum[lane];
        #pragma unroll
        for (int off = 1; off < 32; off <<= 1) {
            int t = __shfl_up_sync(0xffffffff, s, off);
            if (lane >= off) s += t;
        }
        wsum[lane] = s;
    }
    __syncthreads();
    if (wid > 0) x += wsum[wid - 1];
    if (gid < N_NODES) g_rowptr[gid + 1] = x;
    if (tid == SCAN_B - 1) g_blocksum[blockIdx.x] = x;
    if (gid == 0) g_rowptr[0] = 0;
}

// each block computes its own exclusive blocksum prefix (<=48 independent
// L2-hit loads, MLP-covered), then offsets its chunk
__global__ void k_scan3() {
    __shared__ int s_off;
    if (threadIdx.x == 0) {
        int acc = 0;
        #pragma unroll 8
        for (int b = 0; b < N_CHUNK; b++)
            if (b < blockIdx.x) acc += g_blocksum[b];
        s_off = acc;
    }
    __syncthreads();
    int gid = blockIdx.x * SCAN_B + threadIdx.x;
    if (gid < N_NODES) g_rowptr[gid + 1] += s_off;
}

__global__ void k_fill() {
    int i = blockIdx.x * blockDim.x + threadIdx.x;
    if (i >= N_EDGES) return;
    int d = g_dst32[i];
    int pos = g_rowptr[d] + atomicAdd(&g_fill[d], 1);
    g_col[pos] = g_src32[i];
}

// -------- mean aggregation over fp16 table: warp/node, lane owns 2 feats --------
__global__ void k_agg(const __half2* __restrict__ hh, float* __restrict__ agg) {
    int warp = (blockIdx.x * blockDim.x + threadIdx.x) >> 5;
    int lane = threadIdx.x & 31;
    if (warp >= N_NODES) return;
    int s = g_rowptr[warp], e = g_rowptr[warp + 1];
    float2 a0 = make_float2(0.f, 0.f), a1 = make_float2(0.f, 0.f);
    float2 a2 = make_float2(0.f, 0.f), a3 = make_float2(0.f, 0.f);
    int j = s;
    for (; j + 3 < e; j += 4) {
        int c0 = g_col[j], c1 = g_col[j + 1], c2 = g_col[j + 2], c3 = g_col[j + 3];
        float2 v0 = __half22float2(hh[c0 * 32 + lane]);
        float2 v1 = __half22float2(hh[c1 * 32 + lane]);
        float2 v2 = __half22float2(hh[c2 * 32 + lane]);
        float2 v3 = __half22float2(hh[c3 * 32 + lane]);
        a0.x += v0.x; a0.y += v0.y;
        a1.x += v1.x; a1.y += v1.y;
        a2.x += v2.x; a2.y += v2.y;
        a3.x += v3.x; a3.y += v3.y;
    }
    for (; j < e; j++) {
        float2 v = __half22float2(hh[g_col[j] * 32 + lane]);
        a0.x += v.x; a0.y += v.y;
    }
    int deg = e - s;
    float inv = (deg > 0) ? (1.0f / (float)deg) : 0.0f;
    float2 o;
    o.x = ((a0.x + a1.x) + (a2.x + a3.x)) * inv;
    o.y = ((a0.y + a1.y) + (a2.y + a3.y)) * inv;
    ((float2*)agg)[warp * 32 + lane] = o;
}

// -------- fused transform (R1-proven FFMA form + padded smem) --------
// C = act(H@Ws [+ G@Wn] + b); optional fp16 mirror of C for the next gather
template <bool NEIGH, bool RELU>
__global__ void __launch_bounds__(256)
k_transform(const float* __restrict__ H, const float* __restrict__ G,
            const float* __restrict__ Ws, const float* __restrict__ Wn,
            const float* __restrict__ bias, float* __restrict__ C,
            __half2* __restrict__ Chalf) {
    extern __shared__ float sm[];
    float* sWs = sm;                               // 4096 floats
    float* sWn = NEIGH ? (sm + 4096) : nullptr;    // 4096 floats
    float* sH  = NEIGH ? (sm + 8192) : (sm + 4096);  // 64*HSTRIDE
    float* sG  = NEIGH ? (sH + 64 * HSTRIDE) : nullptr;

    int tid = threadIdx.x;
    int n0 = blockIdx.x * 64;

    #pragma unroll
    for (int i = 0; i < 4; i++) {
        int f = tid + i * 256;
        ((float4*)sWs)[f] = ((const float4*)Ws)[f];
        if (NEIGH) ((float4*)sWn)[f] = ((const float4*)Wn)[f];
    }
    #pragma unroll
    for (int i = 0; i < 4; i++) {
        int f = tid + i * 256;
        int row = f >> 4, c = f & 15;
        long g4 = (long)n0 * 16 + f;
        bool ok = (g4 < (long)N_NODES * 16);
        float4 v = ok ? ((const float4*)H)[g4] : make_float4(0.f, 0.f, 0.f, 0.f);
        ((float4*)sH)[row * 17 + c] = v;
        if (NEIGH) {
            float4 u = ok ? ((const float4*)G)[g4] : make_float4(0.f, 0.f, 0.f, 0.f);
            ((float4*)sG)[row * 17 + c] = u;
        }
    }
    __syncthreads();

    int tx = tid & 15;    // output group (4 outputs)
    int ty = tid >> 4;    // node group (4 nodes)

    float4 bv = ((const float4*)bias)[tx];
    float acc[4][4];
    #pragma unroll
    for (int i = 0; i < 4; i++) {
        acc[i][0] = bv.x; acc[i][1] = bv.y; acc[i][2] = bv.z; acc[i][3] = bv.w;
    }

    #pragma unroll 8
    for (int k = 0; k < 64; k++) {
        float4 ws = ((float4*)sWs)[k * 16 + tx];
        #pragma unroll
        for (int i = 0; i < 4; i++) {
            float hv = sH[(ty * 4 + i) * HSTRIDE + k];
            acc[i][0] += hv * ws.x;
            acc[i][1] += hv * ws.y;
            acc[i][2] += hv * ws.z;
            acc[i][3] += hv * ws.w;
        }
        if (NEIGH) {
            float4 wn = ((float4*)sWn)[k * 16 + tx];
            #pragma unroll
            for (int i = 0; i < 4; i++) {
                float gv = sG[(ty * 4 + i) * HSTRIDE + k];
                acc[i][0] += gv * wn.x;
                acc[i][1] += gv * wn.y;
                acc[i][2] += gv * wn.z;
                acc[i][3] += gv * wn.w;
            }
        }
    }

    #pragma unroll
    for (int i = 0; i < 4; i++) {
        int row = n0 + ty * 4 + i;
        if (row < N_NODES) {
            float4 o;
            o.x = RELU ? fmaxf(acc[i][0], 0.f) : acc[i][0];
            o.y = RELU ? fmaxf(acc[i][1], 0.f) : acc[i][1];
            o.z = RELU ? fmaxf(acc[i][2], 0.f) : acc[i][2];
            o.w = RELU ? fmaxf(acc[i][3], 0.f) : acc[i][3];
            ((float4*)C)[row * 16 + tx] = o;
            if (Chalf) {
                Chalf[row * 32 + tx * 2]     = __floats2half2_rn(o.x, o.y);
                Chalf[row * 32 + tx * 2 + 1] = __floats2half2_rn(o.z, o.w);
            }
        }
    }
}

extern "C" void kernel_launch(void* const* d_in, const int* in_sizes, int n_in,
                              void* d_out, int out_size) {
    const float* embed   = (const float*)d_in[0];
    const float* W1_self = (const float*)d_in[1];
    const float* W1_neigh= (const float*)d_in[2];
    const float* b1      = (const float*)d_in[3];
    const float* W2_self = (const float*)d_in[4];
    const float* W2_neigh= (const float*)d_in[5];
    const float* b2      = (const float*)d_in[6];
    const float* W_fc    = (const float*)d_in[7];
    const float* b_fc    = (const float*)d_in[8];
    const int*   ids_w   = (const int*)d_in[9];
    const void*  src     = d_in[10];
    const void*  dst     = d_in[11];
    float* out = (float*)d_out;

    const int SMEM_N = (8192 + 2 * 64 * HSTRIDE) * 4;   // 67584 B
    const int SMEM_F = (4096 + 64 * HSTRIDE) * 4;       // 33792 B
    cudaFuncSetAttribute((const void*)k_transform<true, true>,
                         cudaFuncAttributeMaxDynamicSharedMemorySize, SMEM_N);
    cudaFuncSetAttribute((const void*)k_transform<true, false>,
                         cudaFuncAttributeMaxDynamicSharedMemorySize, SMEM_N);
    cudaFuncSetAttribute((const void*)k_transform<false, false>,
                         cudaFuncAttributeMaxDynamicSharedMemorySize, SMEM_F);

    float*   agg; cudaGetSymbolAddress((void**)&agg, g_agg);
    float*   h1;  cudaGetSymbolAddress((void**)&h1,  g_h1);
    float*   h2;  cudaGetSymbolAddress((void**)&h2,  g_h2);
    __half2* xh;  cudaGetSymbolAddress((void**)&xh,  g_xh);
    __half2* h1h; cudaGetSymbolAddress((void**)&h1h, g_h1h);

    // --- CSR build + embed fp16 convert ---
    k_zero<<<(N_NODES * 32 + 255) / 256, 256>>>(ids_w, embed);
    k_degree<<<(N_EDGES + 255) / 256, 256>>>(src, dst);
    k_scan1<<<N_CHUNK, SCAN_B>>>();
    k_scan3<<<N_CHUNK, SCAN_B>>>();
    k_fill<<<(N_EDGES + 255) / 256, 256>>>();

    const int AGG_BLOCKS = (N_NODES * 32 + 255) / 256;
    const int GEMM_BLOCKS = (N_NODES + 63) / 64;

    // --- Layer 1: gather fp16 embed, transform (also emits fp16 h1) ---
    k_agg<<<AGG_BLOCKS, 256>>>(xh, agg);
    k_transform<true, true><<<GEMM_BLOCKS, 256, SMEM_N>>>(
        embed, agg, W1_self, W1_neigh, b1, h1, h1h);

    // --- Layer 2: gather fp16 h1 ---
    k_agg<<<AGG_BLOCKS, 256>>>(h1h, agg);
    k_transform<true, false><<<GEMM_BLOCKS, 256, SMEM_N>>>(
        h1, agg, W2_self, W2_neigh, b2, h2, nullptr);

    // --- Final linear ---
    k_transform<false, false><<<GEMM_BLOCKS, 256, SMEM_F>>>(
        h2, nullptr, W_fc, nullptr, b_fc, out, nullptr);
}